// round 1
// baseline (speedup 1.0000x reference)
#include <cuda_runtime.h>
#include <cuda_fp16.h>
#include <mma.h>

using namespace nvcuda;

// Problem constants (fixed by the dataset)
#define BB 32
#define SS 2048
#define DD 1024
#define MM (BB * SS)   // 65536 rows of att_hidden

// Scratch (no allocations allowed)
__device__ float g_scores[BB * SS];   // [B, S] pre-softmax scores
__device__ float g_uq[BB * DD];       // [B, D] = rs @ U^T

// ---------------------------------------------------------------------------
// K0: uq[b,d] = sum_e U[d,e] * rs[b,e]  (fp32, warp per output)
//     + zero g_scores (atomic accumulator must reset every replay)
// ---------------------------------------------------------------------------
__global__ void __launch_bounds__(256) init_kernel(const float* __restrict__ U,
                                                   const float* __restrict__ rs) {
    int gtid = blockIdx.x * 256 + threadIdx.x;
    if (gtid < BB * SS) g_scores[gtid] = 0.0f;

    int w = gtid >> 5;        // global warp id, 0..32767
    int lane = gtid & 31;
    if (w < BB * DD / 1) {    // 32768 warps exactly (grid sized for this)
        int b = w >> 10;      // /1024
        int d = w & 1023;
        const float* Urow = U + (size_t)d * DD;
        const float* rb = rs + (size_t)b * DD;
        float acc = 0.0f;
        #pragma unroll 8
        for (int e = lane; e < DD; e += 32) acc += Urow[e] * rb[e];
        #pragma unroll
        for (int o = 16; o > 0; o >>= 1) acc += __shfl_xor_sync(0xffffffffu, acc, o);
        if (lane == 0) g_uq[w] = acc;
    }
}

// ---------------------------------------------------------------------------
// K1: fused proj-GEMM + relu + score reduction.
//   proj[m,n] = sum_k h[m,k] * W[n,k]   (fp16x3 split for fp32-grade accuracy)
//   scores[m] += sum_{n in tile} relu(proj + uq[b,n]) * q[b,n]
// Block tile: 128(M) x 128(N) x 32(K). 8 warps = 4(m) x 2(n), warp = 32x64.
// ---------------------------------------------------------------------------
#define LDT 40   // half-tile leading dim (elements); 80B, 16B-multiple
#define LDE 68   // epilogue fp32 leading dim; 272B, 16B-multiple
#define LO_SCALE 1024.0f
#define LO_INV   (1.0f / 1024.0f)

__global__ void __launch_bounds__(256) gemm_score_kernel(
    const float* __restrict__ h,   // [M, D]
    const float* __restrict__ Wt,  // [D, D] row-major: W[n, k]
    const float* __restrict__ rs)  // [B, D]
{
    // Shared: half tiles (40960B) aliased with epilogue staging (34816B)
    __shared__ __align__(16) unsigned char smraw[40960];
    __half* Ahi = (__half*)smraw;            // 128*40 halves = 10240B
    __half* Alo = Ahi + 128 * LDT;
    __half* Bhi = Alo + 128 * LDT;
    __half* Blo = Bhi + 128 * LDT;
    float*  Es  = (float*)smraw;             // 128*68 fp32 = 34816B (aliased)
    __shared__ float uqs[128];
    __shared__ float qs[128];

    const int tid  = threadIdx.x;
    const int wid  = tid >> 5;
    const int wm   = wid & 3;    // 4 m-warps
    const int wn   = wid >> 2;   // 2 n-warps
    const int m0   = blockIdx.y * 128;
    const int n0   = blockIdx.x * 128;
    const int b    = blockIdx.y >> 4;   // 128 rows per tile, 16 tiles per batch

    if (tid < 128) {
        uqs[tid] = g_uq[b * DD + n0 + tid];
        qs[tid]  = rs[(size_t)b * DD + n0 + tid];
    }

    wmma::fragment<wmma::accumulator, 16, 16, 16, float> acc[2][4];
    wmma::fragment<wmma::accumulator, 16, 16, 16, float> accc[2][4];  // scaled residual
    #pragma unroll
    for (int i = 0; i < 2; i++)
        #pragma unroll
        for (int j = 0; j < 4; j++) {
            wmma::fill_fragment(acc[i][j], 0.0f);
            wmma::fill_fragment(accc[i][j], 0.0f);
        }

    const float* Ag = h  + (size_t)m0 * DD;
    const float* Bg = Wt + (size_t)n0 * DD;

    for (int k0 = 0; k0 < DD; k0 += 32) {
        __syncthreads();
        // Load 128x32 fp32 tiles of A and B; split into fp16 hi + 1024*residual
        #pragma unroll
        for (int it = 0; it < 4; it++) {
            int idx = tid + it * 256;           // 0..1023
            int row = idx >> 3;
            int c4  = (idx & 7) * 4;
            float4 va = *(const float4*)(Ag + (size_t)row * DD + k0 + c4);
            float4 vb = *(const float4*)(Bg + (size_t)row * DD + k0 + c4);
            int so = row * LDT + c4;
            {
                __half h0 = __float2half_rn(va.x), h1 = __float2half_rn(va.y);
                __half h2 = __float2half_rn(va.z), h3 = __float2half_rn(va.w);
                Ahi[so+0]=h0; Ahi[so+1]=h1; Ahi[so+2]=h2; Ahi[so+3]=h3;
                Alo[so+0]=__float2half_rn((va.x-__half2float(h0))*LO_SCALE);
                Alo[so+1]=__float2half_rn((va.y-__half2float(h1))*LO_SCALE);
                Alo[so+2]=__float2half_rn((va.z-__half2float(h2))*LO_SCALE);
                Alo[so+3]=__float2half_rn((va.w-__half2float(h3))*LO_SCALE);
            }
            {
                __half h0 = __float2half_rn(vb.x), h1 = __float2half_rn(vb.y);
                __half h2 = __float2half_rn(vb.z), h3 = __float2half_rn(vb.w);
                Bhi[so+0]=h0; Bhi[so+1]=h1; Bhi[so+2]=h2; Bhi[so+3]=h3;
                Blo[so+0]=__float2half_rn((vb.x-__half2float(h0))*LO_SCALE);
                Blo[so+1]=__float2half_rn((vb.y-__half2float(h1))*LO_SCALE);
                Blo[so+2]=__float2half_rn((vb.z-__half2float(h2))*LO_SCALE);
                Blo[so+3]=__float2half_rn((vb.w-__half2float(h3))*LO_SCALE);
            }
        }
        __syncthreads();

        #pragma unroll
        for (int ks = 0; ks < 2; ks++) {
            wmma::fragment<wmma::matrix_a, 16, 16, 16, __half, wmma::row_major> ah[2], al[2];
            wmma::fragment<wmma::matrix_b, 16, 16, 16, __half, wmma::col_major> bh[4], bl[4];
            #pragma unroll
            for (int i = 0; i < 2; i++) {
                const __half* pa = Ahi + (wm * 32 + i * 16) * LDT + ks * 16;
                wmma::load_matrix_sync(ah[i], pa, LDT);
                wmma::load_matrix_sync(al[i], pa + (Alo - Ahi), LDT);
            }
            #pragma unroll
            for (int j = 0; j < 4; j++) {
                const __half* pb = Bhi + (wn * 64 + j * 16) * LDT + ks * 16;
                wmma::load_matrix_sync(bh[j], pb, LDT);
                wmma::load_matrix_sync(bl[j], pb + (Blo - Bhi), LDT);
            }
            #pragma unroll
            for (int i = 0; i < 2; i++)
                #pragma unroll
                for (int j = 0; j < 4; j++) {
                    wmma::mma_sync(acc[i][j],  ah[i], bh[j], acc[i][j]);   // hi*hi
                    wmma::mma_sync(accc[i][j], ah[i], bl[j], accc[i][j]);  // hi*lo'
                    wmma::mma_sync(accc[i][j], al[i], bh[j], accc[i][j]);  // lo'*hi
                }
        }
    }

    // Fold scaled residual into main accumulator (elementwise, layout-agnostic)
    #pragma unroll
    for (int i = 0; i < 2; i++)
        #pragma unroll
        for (int j = 0; j < 4; j++)
            for (int e = 0; e < acc[i][j].num_elements; e++)
                acc[i][j].x[e] += accc[i][j].x[e] * LO_INV;

    // Epilogue: stage to smem in two 64-col passes, relu(+uq)*q, row-reduce
    float partial = 0.0f;
    const int r  = tid >> 1;
    const int hh = tid & 1;
    #pragma unroll
    for (int jj = 0; jj < 2; jj++) {
        __syncthreads();   // protect aliased smem (tiles / previous Es reads)
        #pragma unroll
        for (int i = 0; i < 2; i++)
            #pragma unroll
            for (int j2 = 0; j2 < 2; j2++)
                wmma::store_matrix_sync(Es + (wm * 32 + i * 16) * LDE + (wn * 32 + j2 * 16),
                                        acc[i][jj * 2 + j2], LDE, wmma::mem_row_major);
        __syncthreads();
        #pragma unroll 8
        for (int c = hh * 32; c < hh * 32 + 32; c++) {
            int l = ((c >> 5) * 64) + jj * 32 + (c & 31);   // local block column
            float v = Es[r * LDE + c] + uqs[l];
            v = fmaxf(v, 0.0f);
            partial += v * qs[l];
        }
    }
    partial += __shfl_xor_sync(0xffffffffu, partial, 1);
    if (hh == 0) atomicAdd(&g_scores[m0 + r], partial);
}

// ---------------------------------------------------------------------------
// K2: softmax over S per batch; weights written to out[B*D ...]
// ---------------------------------------------------------------------------
__global__ void __launch_bounds__(256) softmax_kernel(float* __restrict__ out) {
    const int b = blockIdx.x;
    const int tid = threadIdx.x;
    __shared__ float red[256];
    const float* sc = g_scores + (size_t)b * SS;
    float* wout = out + BB * DD + (size_t)b * SS;

    float mx = -1e30f;
    for (int i = tid; i < SS; i += 256) mx = fmaxf(mx, sc[i]);
    red[tid] = mx; __syncthreads();
    for (int s = 128; s > 0; s >>= 1) {
        if (tid < s) red[tid] = fmaxf(red[tid], red[tid + s]);
        __syncthreads();
    }
    mx = red[0]; __syncthreads();

    float sum = 0.0f;
    for (int i = tid; i < SS; i += 256) {
        float e = expf(sc[i] - mx);
        wout[i] = e;
        sum += e;
    }
    red[tid] = sum; __syncthreads();
    for (int s = 128; s > 0; s >>= 1) {
        if (tid < s) red[tid] += red[tid + s];
        __syncthreads();
    }
    float inv = 1.0f / red[0];
    for (int i = tid; i < SS; i += 256) wout[i] *= inv;
}

// ---------------------------------------------------------------------------
// K3: matched[b,d] = sum_s h[b,s,d] * w[b,s]
// ---------------------------------------------------------------------------
__global__ void __launch_bounds__(256) matched_kernel(const float* __restrict__ h,
                                                      float* __restrict__ out) {
    const int b = blockIdx.y;
    const int d = blockIdx.x * 256 + threadIdx.x;
    __shared__ float ws[SS];
    const float* wout = out + BB * DD + (size_t)b * SS;
    for (int i = threadIdx.x; i < SS; i += 256) ws[i] = wout[i];
    __syncthreads();

    const float* hb = h + (size_t)b * SS * DD + d;
    float acc = 0.0f;
    #pragma unroll 8
    for (int s = 0; s < SS; s++) acc += hb[(size_t)s * DD] * ws[s];
    out[(size_t)b * DD + d] = acc;
}

// ---------------------------------------------------------------------------
extern "C" void kernel_launch(void* const* d_in, const int* in_sizes, int n_in,
                              void* d_out, int out_size) {
    const float* h  = (const float*)d_in[0];  // att_hidden [B,S,D]
    const float* rs = (const float*)d_in[1];  // rnn_state  [1,B,D]
    const float* W  = (const float*)d_in[2];  // W [D,D]
    const float* U  = (const float*)d_in[3];  // U [D,D]
    float* out = (float*)d_out;               // [B*D matched | B*S weights]

    init_kernel<<<4096, 256>>>(U, rs);
    gemm_score_kernel<<<dim3(8, 512), 256>>>(h, W, rs);
    softmax_kernel<<<BB, 256>>>(out);
    matched_kernel<<<dim3(DD / 256, BB), 256>>>(h, out);
}

// round 3
// speedup vs baseline: 1.5307x; 1.5307x over previous
#include <cuda_runtime.h>
#include <cuda_fp16.h>
#include <mma.h>
#include <cstdint>

using namespace nvcuda;

#define BB 32
#define SS 2048
#define DD 1024
#define MM (BB * SS)

#define LO_SCALE 1024.0f
#define LO_INV   0.0009765625f

// ---------------- scratch (static device globals; no runtime alloc) ------
__device__ float  g_scores[BB * SS];
__device__ float  g_uq[BB * DD];
__device__ __half g_Whi[DD * DD];
__device__ __half g_Wlo[DD * DD];
__device__ __half g_Ahi[(size_t)MM * DD];   // 128 MB
__device__ __half g_Alo[(size_t)MM * DD];   // 128 MB

// ---------------- cp.async helpers ---------------------------------------
__device__ __forceinline__ uint32_t smem_u32(const void* p) {
    uint32_t a;
    asm("{ .reg .u64 t; cvta.to.shared.u64 t, %1; cvt.u32.u64 %0, t; }"
        : "=r"(a) : "l"(p));
    return a;
}
__device__ __forceinline__ void cp16(uint32_t dst, const void* src) {
    asm volatile("cp.async.cg.shared.global [%0], [%1], 16;" :: "r"(dst), "l"(src) : "memory");
}
__device__ __forceinline__ void cp_commit() {
    asm volatile("cp.async.commit_group;" ::: "memory");
}
template <int N> __device__ __forceinline__ void cp_wait() {
    asm volatile("cp.async.wait_group %0;" :: "n"(N) : "memory");
}

// ---------------- K_a: split W -> Whi/Wlo --------------------------------
__global__ void __launch_bounds__(256) wsplit_kernel(const float* __restrict__ W) {
    int i = (blockIdx.x * 256 + threadIdx.x) * 4;
    float4 v = *(const float4*)(W + i);
    __half2 h01 = __floats2half2_rn(v.x, v.y);
    __half2 h23 = __floats2half2_rn(v.z, v.w);
    float2 b01 = __half22float2(h01), b23 = __half22float2(h23);
    __half2 l01 = __floats2half2_rn((v.x - b01.x) * LO_SCALE, (v.y - b01.y) * LO_SCALE);
    __half2 l23 = __floats2half2_rn((v.z - b23.x) * LO_SCALE, (v.w - b23.y) * LO_SCALE);
    *(__half2*)(g_Whi + i)     = h01;
    *(__half2*)(g_Whi + i + 2) = h23;
    *(__half2*)(g_Wlo + i)     = l01;
    *(__half2*)(g_Wlo + i + 2) = l23;
}

// ---------------- K_a2: split h -> Ahi/Alo --------------------------------
__global__ void __launch_bounds__(256) asplit_kernel(const float* __restrict__ h) {
    size_t i = ((size_t)blockIdx.x * 256 + threadIdx.x) * 4;
    float4 v = *(const float4*)(h + i);
    __half2 h01 = __floats2half2_rn(v.x, v.y);
    __half2 h23 = __floats2half2_rn(v.z, v.w);
    float2 b01 = __half22float2(h01), b23 = __half22float2(h23);
    __half2 l01 = __floats2half2_rn((v.x - b01.x) * LO_SCALE, (v.y - b01.y) * LO_SCALE);
    __half2 l23 = __floats2half2_rn((v.z - b23.x) * LO_SCALE, (v.w - b23.y) * LO_SCALE);
    *(__half2*)(g_Ahi + i)     = h01;
    *(__half2*)(g_Ahi + i + 2) = h23;
    *(__half2*)(g_Alo + i)     = l01;
    *(__half2*)(g_Alo + i + 2) = l23;
}

// ---------------- K_b: uq = rs @ U^T; zero scores + matched --------------
__global__ void __launch_bounds__(256) init_kernel(const float* __restrict__ U,
                                                   const float* __restrict__ rs,
                                                   float* __restrict__ out) {
    int gtid = blockIdx.x * 256 + threadIdx.x;
    if (gtid < BB * SS) g_scores[gtid] = 0.0f;
    if (gtid < BB * DD) out[gtid] = 0.0f;

    int w = gtid >> 5;
    int lane = gtid & 31;
    if (w < BB * DD) {
        int b = w >> 10;
        int d = w & 1023;
        const float* Urow = U + (size_t)d * DD;
        const float* rb = rs + (size_t)b * DD;
        float acc = 0.0f;
        #pragma unroll 8
        for (int e = lane; e < DD; e += 32) acc += Urow[e] * rb[e];
        #pragma unroll
        for (int o = 16; o > 0; o >>= 1) acc += __shfl_xor_sync(0xffffffffu, acc, o);
        if (lane == 0) g_uq[w] = acc;
    }
}

// ---------------- K_c: pipelined fp16x3 GEMM + relu + score --------------
// Block: 128m x 128n, k-chunks of 64, double-buffered cp.async.
// 8 warps = 2(m) x 4(n); warp tile 64m x 32n.
#define LDH 72                    // halves; 144 B row stride (16B multiple)
#define TILE_B (128 * LDH * 2)    // 18432 B per half-tile
#define STAGE_B (4 * TILE_B)      // Ahi|Alo|Bhi|Blo = 73728 B
#define SMEM_DYN (2 * STAGE_B)    // 147456 B

__device__ __forceinline__ void load_stage(uint32_t st, int m0, int n0, int k0, int tid) {
    #pragma unroll
    for (int it = 0; it < 16; it++) {
        const int idx = tid + it * 256;
        const int arr = idx >> 10;          // compile-time per it (it>>2)
        const int rem = idx & 1023;
        const int row = rem >> 3;
        const int seg = rem & 7;
        const __half* src;
        if      (arr == 0) src = g_Ahi + (size_t)(m0 + row) * DD;
        else if (arr == 1) src = g_Alo + (size_t)(m0 + row) * DD;
        else if (arr == 2) src = g_Whi + (size_t)(n0 + row) * DD;
        else               src = g_Wlo + (size_t)(n0 + row) * DD;
        cp16(st + arr * TILE_B + row * (LDH * 2) + seg * 16, src + k0 + seg * 8);
    }
}

__global__ void __launch_bounds__(256, 1) gemm_score_kernel(const float* __restrict__ rs) {
    extern __shared__ __align__(16) unsigned char dyn[];
    __shared__ float uqs[128], qs[128];

    const int tid = threadIdx.x;
    const int wid = tid >> 5;
    const int wm  = wid & 1;     // 2 m-warps (64 rows each)
    const int wn  = wid >> 1;    // 4 n-warps (32 cols each)
    const int m0  = blockIdx.y * 128;
    const int n0  = blockIdx.x * 128;
    const int b   = blockIdx.y >> 4;

    if (tid < 128) {
        uqs[tid] = g_uq[b * DD + n0 + tid];
        qs[tid]  = rs[(size_t)b * DD + n0 + tid];
    }

    const uint32_t sbase = smem_u32(dyn);

    wmma::fragment<wmma::accumulator, 16, 16, 16, float> acc[4][2], accr[4][2];
    #pragma unroll
    for (int i = 0; i < 4; i++)
        #pragma unroll
        for (int j = 0; j < 2; j++) {
            wmma::fill_fragment(acc[i][j], 0.0f);
            wmma::fill_fragment(accr[i][j], 0.0f);
        }

    load_stage(sbase, m0, n0, 0, tid);
    cp_commit();

    #pragma unroll 1
    for (int s = 0; s < 16; s++) {
        if (s + 1 < 16) {
            load_stage(sbase + ((s + 1) & 1) * STAGE_B, m0, n0, (s + 1) * 64, tid);
            cp_commit();
            cp_wait<1>();
        } else {
            cp_wait<0>();
        }
        __syncthreads();

        const __half* Ahi = (const __half*)(dyn + (s & 1) * STAGE_B);
        const __half* Alo = Ahi + 128 * LDH;
        const __half* Bhi = Alo + 128 * LDH;
        const __half* Blo = Bhi + 128 * LDH;

        #pragma unroll
        for (int ks = 0; ks < 4; ks++) {
            wmma::fragment<wmma::matrix_a, 16, 16, 16, __half, wmma::row_major> ah[4], al[4];
            wmma::fragment<wmma::matrix_b, 16, 16, 16, __half, wmma::col_major> bh[2], bl[2];
            #pragma unroll
            for (int i = 0; i < 4; i++) {
                const __half* pa = Ahi + (wm * 64 + i * 16) * LDH + ks * 16;
                wmma::load_matrix_sync(ah[i], pa, LDH);
                wmma::load_matrix_sync(al[i], pa + 128 * LDH, LDH);
            }
            #pragma unroll
            for (int j = 0; j < 2; j++) {
                const __half* pb = Bhi + (wn * 32 + j * 16) * LDH + ks * 16;
                wmma::load_matrix_sync(bh[j], pb, LDH);
                wmma::load_matrix_sync(bl[j], pb + 128 * LDH, LDH);
            }
            #pragma unroll
            for (int i = 0; i < 4; i++)
                #pragma unroll
                for (int j = 0; j < 2; j++) {
                    wmma::mma_sync(acc[i][j],  ah[i], bh[j], acc[i][j]);
                    wmma::mma_sync(accr[i][j], ah[i], bl[j], accr[i][j]);
                    wmma::mma_sync(accr[i][j], al[i], bh[j], accr[i][j]);
                }
        }
        __syncthreads();   // protect stage buffer before next iter's cp.async
    }

    // fold residual, stage to smem (alias over tile buffers), reduce
    #pragma unroll
    for (int i = 0; i < 4; i++)
        #pragma unroll
        for (int j = 0; j < 2; j++)
            #pragma unroll
            for (int e = 0; e < acc[i][j].num_elements; e++)
                acc[i][j].x[e] += accr[i][j].x[e] * LO_INV;

    float* Es = (float*)dyn;    // 128 x 132 fp32 = 67584 B
    #pragma unroll
    for (int i = 0; i < 4; i++)
        #pragma unroll
        for (int j = 0; j < 2; j++)
            wmma::store_matrix_sync(Es + (wm * 64 + i * 16) * 132 + (wn * 32 + j * 16),
                                    acc[i][j], 132, wmma::mem_row_major);
    __syncthreads();

    const int r  = tid >> 1;
    const int hh = tid & 1;
    float partial = 0.0f;
    #pragma unroll 16
    for (int c = hh * 64; c < hh * 64 + 64; c++) {
        float v = Es[r * 132 + c] + uqs[c];
        partial += fmaxf(v, 0.0f) * qs[c];
    }
    partial += __shfl_xor_sync(0xffffffffu, partial, 1);
    if (hh == 0) atomicAdd(&g_scores[m0 + r], partial);
}

// ---------------- K_d: softmax over S per batch ---------------------------
__global__ void __launch_bounds__(256) softmax_kernel(float* __restrict__ out) {
    const int b = blockIdx.x;
    const int tid = threadIdx.x;
    __shared__ float red[256];
    const float* sc = g_scores + (size_t)b * SS;
    float* wout = out + BB * DD + (size_t)b * SS;

    float mx = -1e30f;
    for (int i = tid; i < SS; i += 256) mx = fmaxf(mx, sc[i]);
    red[tid] = mx; __syncthreads();
    for (int s = 128; s > 0; s >>= 1) {
        if (tid < s) red[tid] = fmaxf(red[tid], red[tid + s]);
        __syncthreads();
    }
    mx = red[0]; __syncthreads();

    float sum = 0.0f;
    for (int i = tid; i < SS; i += 256) {
        float e = expf(sc[i] - mx);
        wout[i] = e;
        sum += e;
    }
    red[tid] = sum; __syncthreads();
    for (int s = 128; s > 0; s >>= 1) {
        if (tid < s) red[tid] += red[tid + s];
        __syncthreads();
    }
    float inv = 1.0f / red[0];
    for (int i = tid; i < SS; i += 256) wout[i] *= inv;
}

// ---------------- K_e: matched[b,d] += sum_{s chunk} h*w ------------------
__global__ void __launch_bounds__(256) matched_kernel(const float* __restrict__ h,
                                                      float* __restrict__ out) {
    const int b  = blockIdx.y;
    const int sc = blockIdx.z;
    const int d  = blockIdx.x * 256 + threadIdx.x;
    __shared__ float ws[256];
    const float* w = out + BB * DD + (size_t)b * SS + sc * 256;
    ws[threadIdx.x] = w[threadIdx.x];
    __syncthreads();

    const float* hb = h + ((size_t)b * SS + sc * 256) * DD + d;
    float acc = 0.0f;
    #pragma unroll 8
    for (int s = 0; s < 256; s++) acc += hb[(size_t)s * DD] * ws[s];
    atomicAdd(&out[(size_t)b * DD + d], acc);
}

// ---------------------------------------------------------------------------
extern "C" void kernel_launch(void* const* d_in, const int* in_sizes, int n_in,
                              void* d_out, int out_size) {
    const float* h  = (const float*)d_in[0];
    const float* rs = (const float*)d_in[1];
    const float* W  = (const float*)d_in[2];
    const float* U  = (const float*)d_in[3];
    float* out = (float*)d_out;

    cudaFuncSetAttribute(gemm_score_kernel,
                         cudaFuncAttributeMaxDynamicSharedMemorySize, SMEM_DYN);

    wsplit_kernel<<<1024, 256>>>(W);
    asplit_kernel<<<65536, 256>>>(h);
    init_kernel<<<4096, 256>>>(U, rs, out);
    gemm_score_kernel<<<dim3(8, 512), 256, SMEM_DYN>>>(rs);
    softmax_kernel<<<BB, 256>>>(out);
    matched_kernel<<<dim3(DD / 256, BB, 8), 256>>>(h, out);
}